// round 5
// baseline (speedup 1.0000x reference)
#include <cuda_runtime.h>
#include <cuda_fp16.h>
#include <cuda_fp8.h>
#include <stdint.h>

// Problem dims (fixed)
#define MTOT   8192     // B*T
#define SEQ    2048
#define N1     8192     // 2*d_inner
#define K1     2048     // d_model
#define DINNER 4096
#define N2     2048     // d_model
#define K2     4096     // d_inner

#define ASCALE 4096.0f
#define BSCALE 32.0f
#define INVSC  (1.0f / (4096.0f * 32.0f))

// ---------------- scratch (device globals; no runtime alloc) ----------------
__device__ float   g_xproj[(size_t)MTOT * N1];     // 256 MB
__device__ __half  g_x_hi [(size_t)MTOT * K1];
__device__ uint8_t g_x_lo8[(size_t)MTOT * K1];
__device__ __half  g_wi_hi[(size_t)N1 * K1];
__device__ uint8_t g_wi_8 [(size_t)N1 * K1];
__device__ __half  g_h_hi [(size_t)MTOT * K2];
__device__ uint8_t g_h_lo8[(size_t)MTOT * K2];
__device__ __half  g_wo_hi[(size_t)N2 * K2];
__device__ uint8_t g_wo_8 [(size_t)N2 * K2];

// ---------------- PTX helpers (legal on plain sm_103) ----------------
__device__ __forceinline__ uint32_t smem_u32(const void* p) {
    uint32_t a;
    asm("{ .reg .u64 t; cvta.to.shared.u64 t, %1; cvt.u32.u64 %0, t; }" : "=r"(a) : "l"(p));
    return a;
}
#define MBAR_INIT(a, c) \
    asm volatile("mbarrier.init.shared.b64 [%0], %1;" :: "r"(a), "r"(c) : "memory")
#define MBAR_EXPECT_TX(a, b) \
    asm volatile("mbarrier.arrive.expect_tx.shared.b64 _, [%0], %1;" :: "r"(a), "r"(b) : "memory")
#define MBAR_ARRIVE(a) \
    asm volatile("mbarrier.arrive.shared.b64 _, [%0];" :: "r"(a) : "memory")
#define MBAR_WAIT(a, ph) do {                                                      \
    uint32_t _m = (a), _p = (ph), _d;                                              \
    asm volatile("{ .reg .pred p; mbarrier.try_wait.parity.acquire.cta.shared::cta.b64 p, [%1], %2;" \
                 " selp.b32 %0, 1, 0, p; }" : "=r"(_d) : "r"(_m), "r"(_p) : "memory"); \
    if (!_d) {                                                                     \
        asm volatile("{ .reg .pred P;\n"                                           \
                     "W%=: mbarrier.try_wait.parity.acquire.cta.shared::cta.b64 P, [%0], %1, 0x989680;\n" \
                     "@P bra.uni D%=;\n bra.uni W%=;\nD%=: }"                      \
                     :: "r"(_m), "r"(_p) : "memory");                              \
    } } while (0)
#define BULK_G2S(sa, gp, bytes, mb) \
    asm volatile("cp.async.bulk.shared::cluster.global.mbarrier::complete_tx::bytes [%0], [%1], %2, [%3];" \
                 :: "r"(sa), "l"(gp), "r"(bytes), "r"(mb) : "memory")

__device__ __forceinline__ void ldsm_x4(uint32_t* r, uint32_t addr) {
    asm volatile("ldmatrix.sync.aligned.m8n8.x4.shared.b16 {%0,%1,%2,%3}, [%4];"
                 : "=r"(r[0]), "=r"(r[1]), "=r"(r[2]), "=r"(r[3]) : "r"(addr));
}
__device__ __forceinline__ void mma_f16(float* d, const uint32_t* a, const uint32_t* b) {
    asm volatile("mma.sync.aligned.m16n8k16.row.col.f32.f16.f16.f32 "
                 "{%0,%1,%2,%3},{%4,%5,%6,%7},{%8,%9},{%0,%1,%2,%3};"
                 : "+f"(d[0]), "+f"(d[1]), "+f"(d[2]), "+f"(d[3])
                 : "r"(a[0]), "r"(a[1]), "r"(a[2]), "r"(a[3]), "r"(b[0]), "r"(b[1]));
}
// fp8 e4m3 MMA, k32, f16 accumulators (correction term only needs ~8 bits)
__device__ __forceinline__ void mma_f8(uint32_t* d, const uint32_t* a, const uint32_t* b) {
    asm volatile("mma.sync.aligned.m16n8k32.row.col.f16.e4m3.e4m3.f16 "
                 "{%0,%1},{%2,%3,%4,%5},{%6,%7},{%0,%1};"
                 : "+r"(d[0]), "+r"(d[1])
                 : "r"(a[0]), "r"(a[1]), "r"(a[2]), "r"(a[3]), "r"(b[0]), "r"(b[1]));
}

__device__ __forceinline__ uint8_t to_e4m3(float v) {
    return (uint8_t)__nv_cvt_float_to_fp8(v, __NV_SATFINITE, __NV_E4M3);
}

// fp16 tiled layout: 128 rows x 64 fp16 (16 KB) tiles, k-tile fastest, SW128 swizzle.
__device__ __forceinline__ size_t tiled_off(int r, int c, int K) {
    size_t tile = ((size_t)(r >> 7) * (size_t)(K >> 6) + (size_t)(c >> 6)) << 14;
    uint32_t off = ((uint32_t)(r & 127) << 7) | ((uint32_t)(c & 63) << 1);
    off ^= (off >> 3) & 0x70;
    return tile + off;
}
// fp8 tiled layout: 128 rows x 128 fp8 (16 KB) tiles — byte-identical geometry.
__device__ __forceinline__ size_t tiled_off8(int r, int c, int K) {
    size_t tile = ((size_t)(r >> 7) * (size_t)(K >> 7) + (size_t)(c >> 7)) << 14;
    uint32_t off = ((uint32_t)(r & 127) << 7) | (uint32_t)(c & 127);
    off ^= (off >> 3) & 0x70;
    return tile + off;
}

__device__ __forceinline__ uint2 pack8_e4m3(const float* v, float scale) {
    uint32_t lo = 0, hi = 0;
#pragma unroll
    for (int j = 0; j < 4; j++) lo |= (uint32_t)to_e4m3(v[j] * scale) << (8 * j);
#pragma unroll
    for (int j = 0; j < 4; j++) hi |= (uint32_t)to_e4m3(v[4 + j] * scale) << (8 * j);
    return make_uint2(lo, hi);
}

// ---------------- split fp32 -> hi fp16 tile + lo8 fp8 tile (A operands) ----------------
__global__ void split_a(const float* __restrict__ src, __half* __restrict__ hi,
                        uint8_t* __restrict__ lo8, int total8, int K, int kshift) {
    int idx = blockIdx.x * blockDim.x + threadIdx.x;
    if (idx >= total8) return;
    int e0 = idx << 3;
    int r = e0 >> kshift;
    int c = e0 & (K - 1);
    const float* p = src + (size_t)r * K + c;
    float4 v0 = *reinterpret_cast<const float4*>(p);
    float4 v1 = *reinterpret_cast<const float4*>(p + 4);
    float xs[8] = {v0.x, v0.y, v0.z, v0.w, v1.x, v1.y, v1.z, v1.w};
    __align__(16) __half hv[8];
    float lv[8];
#pragma unroll
    for (int j = 0; j < 8; j++) {
        __half h = __float2half_rn(xs[j]);
        hv[j] = h;
        lv[j] = xs[j] - __half2float(h);
    }
    *reinterpret_cast<uint4*>((char*)hi + tiled_off(r, c, K)) = *reinterpret_cast<const uint4*>(hv);
    *reinterpret_cast<uint2*>((char*)lo8 + tiled_off8(r, c, K)) = pack8_e4m3(lv, ASCALE);
}

// ---------------- split fp32 -> hi fp16 tile + fp8(x*32) tile (B operands) ----------------
__global__ void split_b(const float* __restrict__ src, __half* __restrict__ hi,
                        uint8_t* __restrict__ b8, int total8, int K, int kshift) {
    int idx = blockIdx.x * blockDim.x + threadIdx.x;
    if (idx >= total8) return;
    int e0 = idx << 3;
    int r = e0 >> kshift;
    int c = e0 & (K - 1);
    const float* p = src + (size_t)r * K + c;
    float4 v0 = *reinterpret_cast<const float4*>(p);
    float4 v1 = *reinterpret_cast<const float4*>(p + 4);
    float xs[8] = {v0.x, v0.y, v0.z, v0.w, v1.x, v1.y, v1.z, v1.w};
    __align__(16) __half hv[8];
    float hf[8];
#pragma unroll
    for (int j = 0; j < 8; j++) {
        __half h = __float2half_rn(xs[j]);
        hv[j] = h;
        hf[j] = __half2float(h);
    }
    *reinterpret_cast<uint4*>((char*)hi + tiled_off(r, c, K)) = *reinterpret_cast<const uint4*>(hv);
    *reinterpret_cast<uint2*>((char*)b8 + tiled_off8(r, c, K)) = pack8_e4m3(hf, BSCALE);
}

// ------- depthwise causal conv(4) + SiLU gate, output hi fp16 + lo8 fp8 -------
__global__ void conv_gate_split(const float* __restrict__ xp, const float* __restrict__ cw,
                                const float* __restrict__ cb, const float* __restrict__ Dv,
                                __half* __restrict__ hhi, uint8_t* __restrict__ hlo8) {
    int idx = blockIdx.x * blockDim.x + threadIdx.x;
    if (idx >= (MTOT * DINNER) / 8) return;
    int d0 = (idx & 511) << 3;
    int m  = idx >> 9;
    int t  = m & (SEQ - 1);
    const float* row = xp + (size_t)m * N1 + d0;

    float acc[8];
    {
        float4 b0 = *reinterpret_cast<const float4*>(cb + d0);
        float4 b1 = *reinterpret_cast<const float4*>(cb + d0 + 4);
        acc[0]=b0.x; acc[1]=b0.y; acc[2]=b0.z; acc[3]=b0.w;
        acc[4]=b1.x; acc[5]=b1.y; acc[6]=b1.z; acc[7]=b1.w;
    }
    float4 cwv[8];
#pragma unroll
    for (int e = 0; e < 8; e++) cwv[e] = *reinterpret_cast<const float4*>(cw + (size_t)(d0 + e) * 4);

#pragma unroll
    for (int j = 0; j < 4; j++) {
        if (t >= j) {
            const float* rp = row - (size_t)j * N1;
            float4 a = *reinterpret_cast<const float4*>(rp);
            float4 b = *reinterpret_cast<const float4*>(rp + 4);
            float xv[8] = {a.x, a.y, a.z, a.w, b.x, b.y, b.z, b.w};
#pragma unroll
            for (int e = 0; e < 8; e++) {
                float w = (j == 0) ? cwv[e].w : (j == 1) ? cwv[e].z : (j == 2) ? cwv[e].y : cwv[e].x;
                acc[e] = fmaf(xv[e], w, acc[e]);
            }
        }
    }
    float4 g0 = *reinterpret_cast<const float4*>(row + DINNER);
    float4 g1 = *reinterpret_cast<const float4*>(row + DINNER + 4);
    float gv[8] = {g0.x, g0.y, g0.z, g0.w, g1.x, g1.y, g1.z, g1.w};
    float4 dv0 = *reinterpret_cast<const float4*>(Dv + d0);
    float4 dv1 = *reinterpret_cast<const float4*>(Dv + d0 + 4);
    float dv[8] = {dv0.x, dv0.y, dv0.z, dv0.w, dv1.x, dv1.y, dv1.z, dv1.w};

    __align__(16) __half hv[8];
    float lv[8];
#pragma unroll
    for (int e = 0; e < 8; e++) {
        float s1 = acc[e] / (1.f + __expf(-acc[e]));
        float s2 = gv[e] / (1.f + __expf(-gv[e]));
        float val = s1 * dv[e] * s2;
        __half h = __float2half_rn(val);
        hv[e] = h;
        lv[e] = val - __half2float(h);
    }
    *reinterpret_cast<uint4*>((char*)hhi + tiled_off(m, d0, K2)) = *reinterpret_cast<const uint4*>(hv);
    *reinterpret_cast<uint2*>((char*)hlo8 + tiled_off8(m, d0, K2)) = pack8_e4m3(lv, ASCALE);
}

// ---- fp16 + fp8-correction GEMM: C = Ahi*Bhi^T + (Alo8*B8^T)/2^17 ----
// CTA 128x128, stage = k128: Ahi x2, Bhi x2, Alo8, B8 (6 x 16 KB = 96 KB), 2 stages.
#define TILE_BYTES  16384
#define STAGE_BYTES (6 * TILE_BYTES)
#define NSTAGE      2
#define SMEM_REQ    (NSTAGE * STAGE_BYTES + 1024 + 128)

__global__ void __launch_bounds__(288, 1)
gemm_f16f8(const __half* __restrict__ Ahi, const uint8_t* __restrict__ Alo8,
           const __half* __restrict__ Bhi, const uint8_t* __restrict__ B8,
           float* __restrict__ C, int M, int N, int K) {
    extern __shared__ char smem_raw[];
    uint32_t sbase = (smem_u32(smem_raw) + 1023) & ~1023u;
    const int tid = threadIdx.x, wid = tid >> 5, lane = tid & 31;
    const int m0 = blockIdx.y * 128, n0 = blockIdx.x * 128;
    const int KT128 = K >> 7, KT64 = K >> 6;
    const uint32_t bar = sbase + NSTAGE * STAGE_BYTES;

    if (tid == 0) {
#pragma unroll
        for (int s = 0; s < NSTAGE; s++) {
            MBAR_INIT(bar + 8 * s, 1);
            MBAR_INIT(bar + 64 + 8 * s, 8);
        }
    }
    __syncthreads();

    if (wid == 8) {
        if (lane == 0) {
            const char* pAh = (const char*)Ahi + ((size_t)(m0 >> 7) * KT64 << 14);
            const char* pA8 = (const char*)Alo8 + ((size_t)(m0 >> 7) * KT128 << 14);
            const char* pBh = (const char*)Bhi + ((size_t)(n0 >> 7) * KT64 << 14);
            const char* pB8 = (const char*)B8 + ((size_t)(n0 >> 7) * KT128 << 14);
            int eph[NSTAGE] = {1, 1};
            int s = 0;
            for (int i = 0; i < KT128; i++) {
                MBAR_WAIT(bar + 64 + 8 * s, eph[s]);
                eph[s] ^= 1;
                MBAR_EXPECT_TX(bar + 8 * s, (uint32_t)STAGE_BYTES);
                uint32_t st = sbase + s * STAGE_BYTES;
                size_t k16 = (size_t)(2 * i) << 14;
                size_t k8  = (size_t)i << 14;
                BULK_G2S(st,                  pAh + k16,              TILE_BYTES, bar + 8 * s);
                BULK_G2S(st + TILE_BYTES,     pAh + k16 + TILE_BYTES, TILE_BYTES, bar + 8 * s);
                BULK_G2S(st + 2 * TILE_BYTES, pBh + k16,              TILE_BYTES, bar + 8 * s);
                BULK_G2S(st + 3 * TILE_BYTES, pBh + k16 + TILE_BYTES, TILE_BYTES, bar + 8 * s);
                BULK_G2S(st + 4 * TILE_BYTES, pA8 + k8,               TILE_BYTES, bar + 8 * s);
                BULK_G2S(st + 5 * TILE_BYTES, pB8 + k8,               TILE_BYTES, bar + 8 * s);
                if (++s == NSTAGE) s = 0;
            }
        }
        return;
    }

    // ---- compute warps 0..7: warp tile 64(m) x 32(n) ----
    const int wm = wid >> 2, wn = wid & 3;

    uint32_t a_off[4], a_msk[4];
#pragma unroll
    for (int i = 0; i < 4; i++) {
        uint32_t row = wm * 64 + i * 16 + (lane & 15);
        uint32_t off = (row << 7) | ((lane >> 4) << 4);
        a_off[i] = off;
        a_msk[i] = (off >> 3) & 0x70;
    }
    uint32_t b_off[2], b_msk[2];
#pragma unroll
    for (int p = 0; p < 2; p++) {
        uint32_t row = wn * 32 + p * 16 + ((lane >> 4) << 3) + (lane & 7);
        uint32_t off = (row << 7) | (((lane >> 3) & 1) << 4);
        b_off[p] = off;
        b_msk[p] = (off >> 3) & 0x70;
    }

    float accH[4][4][4];
    uint32_t accL[4][4][2];
#pragma unroll
    for (int i = 0; i < 4; i++)
#pragma unroll
        for (int j = 0; j < 4; j++) {
#pragma unroll
            for (int e = 0; e < 4; e++) accH[i][j][e] = 0.f;
            accL[i][j][0] = 0u; accL[i][j][1] = 0u;
        }

    int fph[NSTAGE] = {0, 0};
    int s = 0;
    for (int it = 0; it < KT128; it++) {
        MBAR_WAIT(bar + 8 * s, fph[s]);
        fph[s] ^= 1;
        uint32_t st = sbase + s * STAGE_BYTES;
        uint32_t s8a = st + 4 * TILE_BYTES, s8b = st + 5 * TILE_BYTES;

#pragma unroll
        for (int half = 0; half < 2; half++) {
            uint32_t sA = st + half * TILE_BYTES;
            uint32_t sB = st + (2 + half) * TILE_BYTES;
            // fp16 hi pass: 4 k16 steps in this half
#pragma unroll
            for (int ks = 0; ks < 4; ks++) {
                uint32_t kb = ks * 32;
                uint32_t ah[4][4], bh[4][2];
#pragma unroll
                for (int i = 0; i < 4; i++)
                    ldsm_x4(ah[i], sA + ((a_off[i] + kb) ^ a_msk[i]));
#pragma unroll
                for (int p = 0; p < 2; p++) {
                    uint32_t r[4];
                    ldsm_x4(r, sB + ((b_off[p] + kb) ^ b_msk[p]));
                    bh[2 * p][0] = r[0]; bh[2 * p][1] = r[1];
                    bh[2 * p + 1][0] = r[2]; bh[2 * p + 1][1] = r[3];
                }
#pragma unroll
                for (int i = 0; i < 4; i++)
#pragma unroll
                    for (int j = 0; j < 4; j++)
                        mma_f16(accH[i][j], ah[i], bh[j]);
            }
            // fp8 correction: 2 k32 steps in this half
#pragma unroll
            for (int q = 0; q < 2; q++) {
                uint32_t kb = (half * 2 + q) * 32;
                uint32_t a8[4][4], b8[4][2];
#pragma unroll
                for (int i = 0; i < 4; i++)
                    ldsm_x4(a8[i], s8a + ((a_off[i] + kb) ^ a_msk[i]));
#pragma unroll
                for (int p = 0; p < 2; p++) {
                    uint32_t r[4];
                    ldsm_x4(r, s8b + ((b_off[p] + kb) ^ b_msk[p]));
                    b8[2 * p][0] = r[0]; b8[2 * p][1] = r[1];
                    b8[2 * p + 1][0] = r[2]; b8[2 * p + 1][1] = r[3];
                }
#pragma unroll
                for (int i = 0; i < 4; i++)
#pragma unroll
                    for (int j = 0; j < 4; j++)
                        mma_f8(accL[i][j], a8[i], b8[j]);
            }
        }
        __syncwarp();
        if (lane == 0) MBAR_ARRIVE(bar + 64 + 8 * s);
        if (++s == NSTAGE) s = 0;
    }

    // ---- epilogue: accH + INVSC*accL -> C ----
    const int g_row = lane >> 2;
    const int g_col = (lane & 3) * 2;
#pragma unroll
    for (int i = 0; i < 4; i++) {
        size_t r0 = (size_t)m0 + wm * 64 + i * 16 + g_row;
#pragma unroll
        for (int j = 0; j < 4; j++) {
            int c = n0 + wn * 32 + j * 8 + g_col;
            float2 l01 = __half22float2(*reinterpret_cast<__half2*>(&accL[i][j][0]));
            float2 l23 = __half22float2(*reinterpret_cast<__half2*>(&accL[i][j][1]));
            float2 v0 = make_float2(accH[i][j][0] + INVSC * l01.x, accH[i][j][1] + INVSC * l01.y);
            float2 v1 = make_float2(accH[i][j][2] + INVSC * l23.x, accH[i][j][3] + INVSC * l23.y);
            *reinterpret_cast<float2*>(&C[r0 * N + c])       = v0;
            *reinterpret_cast<float2*>(&C[(r0 + 8) * N + c]) = v1;
        }
    }
}

// ---------------- launch ----------------
extern "C" void kernel_launch(void* const* d_in, const int* in_sizes, int n_in,
                              void* d_out, int out_size) {
    const float* x      = (const float*)d_in[0];
    const float* w_in   = (const float*)d_in[1];
    const float* w_out  = (const float*)d_in[2];
    const float* conv_w = (const float*)d_in[3];
    const float* conv_b = (const float*)d_in[4];
    const float* Dvec   = (const float*)d_in[5];
    float* out = (float*)d_out;

    float* xp; __half *xhi, *wihi, *hhi, *wohi; uint8_t *xlo8, *wi8, *hlo8, *wo8;
    cudaGetSymbolAddress((void**)&xp,   g_xproj);
    cudaGetSymbolAddress((void**)&xhi,  g_x_hi);
    cudaGetSymbolAddress((void**)&xlo8, g_x_lo8);
    cudaGetSymbolAddress((void**)&wihi, g_wi_hi);
    cudaGetSymbolAddress((void**)&wi8,  g_wi_8);
    cudaGetSymbolAddress((void**)&hhi,  g_h_hi);
    cudaGetSymbolAddress((void**)&hlo8, g_h_lo8);
    cudaGetSymbolAddress((void**)&wohi, g_wo_hi);
    cudaGetSymbolAddress((void**)&wo8,  g_wo_8);

    cudaFuncSetAttribute(gemm_f16f8, cudaFuncAttributeMaxDynamicSharedMemorySize, SMEM_REQ);

    {
        int t8 = MTOT * K1 / 8;
        split_a<<<(t8 + 255) / 256, 256>>>(x, xhi, xlo8, t8, K1, 11);
    }
    {
        int t8 = N1 * K1 / 8;
        split_b<<<(t8 + 255) / 256, 256>>>(w_in, wihi, wi8, t8, K1, 11);
    }
    {
        int t8 = N2 * K2 / 8;
        split_b<<<(t8 + 255) / 256, 256>>>(w_out, wohi, wo8, t8, K2, 12);
    }

    // GEMM1: xproj[8192,8192] = x @ w_in^T
    gemm_f16f8<<<dim3(N1 / 128, MTOT / 128), 288, SMEM_REQ>>>(xhi, xlo8, wihi, wi8, xp, MTOT, N1, K1);

    // conv + gate -> h (fp16 hi + fp8 lo)
    {
        int t8 = MTOT * DINNER / 8;
        conv_gate_split<<<(t8 + 255) / 256, 256>>>(xp, conv_w, conv_b, Dvec, hhi, hlo8);
    }

    // GEMM2: out[8192,2048] = h @ w_out^T
    gemm_f16f8<<<dim3(N2 / 128, MTOT / 128), 288, SMEM_REQ>>>(hhi, hlo8, wohi, wo8, out, MTOT, N2, K2);
}

// round 6
// speedup vs baseline: 1.9004x; 1.9004x over previous
#include <cuda_runtime.h>
#include <cuda_fp16.h>
#include <stdint.h>

// Problem dims (fixed)
#define MTOT   8192     // B*T
#define SEQ    2048
#define N1     8192     // 2*d_inner
#define K1     2048     // d_model
#define DINNER 4096
#define N2     2048     // d_model
#define K2     4096     // d_inner

// ---------------- scratch (device globals; no runtime alloc) ----------------
__device__ float  g_xproj[(size_t)MTOT * N1];     // 256 MB
__device__ __half g_x_hi [(size_t)MTOT * K1];
__device__ __half g_wi_hi[(size_t)N1 * K1];
__device__ __half g_h_hi [(size_t)MTOT * K2];
__device__ __half g_wo_hi[(size_t)N2 * K2];

// ---------------- PTX helpers (legal on plain sm_103) ----------------
__device__ __forceinline__ uint32_t smem_u32(const void* p) {
    uint32_t a;
    asm("{ .reg .u64 t; cvta.to.shared.u64 t, %1; cvt.u32.u64 %0, t; }" : "=r"(a) : "l"(p));
    return a;
}
#define MBAR_INIT(a, c) \
    asm volatile("mbarrier.init.shared.b64 [%0], %1;" :: "r"(a), "r"(c) : "memory")
#define MBAR_EXPECT_TX(a, b) \
    asm volatile("mbarrier.arrive.expect_tx.shared.b64 _, [%0], %1;" :: "r"(a), "r"(b) : "memory")
#define MBAR_ARRIVE(a) \
    asm volatile("mbarrier.arrive.shared.b64 _, [%0];" :: "r"(a) : "memory")
#define MBAR_WAIT(a, ph) do {                                                      \
    uint32_t _m = (a), _p = (ph), _d;                                              \
    asm volatile("{ .reg .pred p; mbarrier.try_wait.parity.acquire.cta.shared::cta.b64 p, [%1], %2;" \
                 " selp.b32 %0, 1, 0, p; }" : "=r"(_d) : "r"(_m), "r"(_p) : "memory"); \
    if (!_d) {                                                                     \
        asm volatile("{ .reg .pred P;\n"                                           \
                     "W%=: mbarrier.try_wait.parity.acquire.cta.shared::cta.b64 P, [%0], %1, 0x989680;\n" \
                     "@P bra.uni D%=;\n bra.uni W%=;\nD%=: }"                      \
                     :: "r"(_m), "r"(_p) : "memory");                              \
    } } while (0)
#define BULK_G2S(sa, gp, bytes, mb) \
    asm volatile("cp.async.bulk.shared::cluster.global.mbarrier::complete_tx::bytes [%0], [%1], %2, [%3];" \
                 :: "r"(sa), "l"(gp), "r"(bytes), "r"(mb) : "memory")

__device__ __forceinline__ void ldsm_x4(uint32_t* r, uint32_t addr) {
    asm volatile("ldmatrix.sync.aligned.m8n8.x4.shared.b16 {%0,%1,%2,%3}, [%4];"
                 : "=r"(r[0]), "=r"(r[1]), "=r"(r[2]), "=r"(r[3]) : "r"(addr));
}
__device__ __forceinline__ void mma_f16(float* d, const uint32_t* a, const uint32_t* b) {
    asm volatile("mma.sync.aligned.m16n8k16.row.col.f32.f16.f16.f32 "
                 "{%0,%1,%2,%3},{%4,%5,%6,%7},{%8,%9},{%0,%1,%2,%3};"
                 : "+f"(d[0]), "+f"(d[1]), "+f"(d[2]), "+f"(d[3])
                 : "r"(a[0]), "r"(a[1]), "r"(a[2]), "r"(a[3]), "r"(b[0]), "r"(b[1]));
}

// fp16 tiled layout: 128 rows x 64 fp16 (16 KB) tiles, k-tile fastest, SW128 swizzle.
__device__ __forceinline__ size_t tiled_off(int r, int c, int K) {
    size_t tile = ((size_t)(r >> 7) * (size_t)(K >> 6) + (size_t)(c >> 6)) << 14;
    uint32_t off = ((uint32_t)(r & 127) << 7) | ((uint32_t)(c & 63) << 1);
    off ^= (off >> 3) & 0x70;
    return tile + off;
}

// ---------------- convert fp32 -> fp16 in tiled layout ----------------
__global__ void cvt_f16_tiled(const float* __restrict__ src, __half* __restrict__ hi,
                              int total8, int K, int kshift) {
    int idx = blockIdx.x * blockDim.x + threadIdx.x;
    if (idx >= total8) return;
    int e0 = idx << 3;
    int r = e0 >> kshift;
    int c = e0 & (K - 1);
    const float* p = src + (size_t)r * K + c;
    float4 v0 = *reinterpret_cast<const float4*>(p);
    float4 v1 = *reinterpret_cast<const float4*>(p + 4);
    float xs[8] = {v0.x, v0.y, v0.z, v0.w, v1.x, v1.y, v1.z, v1.w};
    __align__(16) __half hv[8];
#pragma unroll
    for (int j = 0; j < 8; j++) hv[j] = __float2half_rn(xs[j]);
    *reinterpret_cast<uint4*>((char*)hi + tiled_off(r, c, K)) = *reinterpret_cast<const uint4*>(hv);
}

// ------- depthwise causal conv(4) + SiLU gate -> fp16 tiled -------
__global__ void conv_gate_f16(const float* __restrict__ xp, const float* __restrict__ cw,
                              const float* __restrict__ cb, const float* __restrict__ Dv,
                              __half* __restrict__ hhi) {
    int idx = blockIdx.x * blockDim.x + threadIdx.x;
    if (idx >= (MTOT * DINNER) / 8) return;
    int d0 = (idx & 511) << 3;
    int m  = idx >> 9;
    int t  = m & (SEQ - 1);
    const float* row = xp + (size_t)m * N1 + d0;

    float acc[8];
    {
        float4 b0 = *reinterpret_cast<const float4*>(cb + d0);
        float4 b1 = *reinterpret_cast<const float4*>(cb + d0 + 4);
        acc[0]=b0.x; acc[1]=b0.y; acc[2]=b0.z; acc[3]=b0.w;
        acc[4]=b1.x; acc[5]=b1.y; acc[6]=b1.z; acc[7]=b1.w;
    }
    float4 cwv[8];
#pragma unroll
    for (int e = 0; e < 8; e++) cwv[e] = *reinterpret_cast<const float4*>(cw + (size_t)(d0 + e) * 4);

#pragma unroll
    for (int j = 0; j < 4; j++) {
        if (t >= j) {
            const float* rp = row - (size_t)j * N1;
            float4 a = *reinterpret_cast<const float4*>(rp);
            float4 b = *reinterpret_cast<const float4*>(rp + 4);
            float xv[8] = {a.x, a.y, a.z, a.w, b.x, b.y, b.z, b.w};
#pragma unroll
            for (int e = 0; e < 8; e++) {
                float w = (j == 0) ? cwv[e].w : (j == 1) ? cwv[e].z : (j == 2) ? cwv[e].y : cwv[e].x;
                acc[e] = fmaf(xv[e], w, acc[e]);
            }
        }
    }
    float4 g0 = *reinterpret_cast<const float4*>(row + DINNER);
    float4 g1 = *reinterpret_cast<const float4*>(row + DINNER + 4);
    float gv[8] = {g0.x, g0.y, g0.z, g0.w, g1.x, g1.y, g1.z, g1.w};
    float4 dv0 = *reinterpret_cast<const float4*>(Dv + d0);
    float4 dv1 = *reinterpret_cast<const float4*>(Dv + d0 + 4);
    float dv[8] = {dv0.x, dv0.y, dv0.z, dv0.w, dv1.x, dv1.y, dv1.z, dv1.w};

    __align__(16) __half hv[8];
#pragma unroll
    for (int e = 0; e < 8; e++) {
        float s1 = acc[e] / (1.f + __expf(-acc[e]));
        float s2 = gv[e] / (1.f + __expf(-gv[e]));
        hv[e] = __float2half_rn(s1 * dv[e] * s2);
    }
    *reinterpret_cast<uint4*>((char*)hhi + tiled_off(m, d0, K2)) = *reinterpret_cast<const uint4*>(hv);
}

// ---------------- fp16 HMMA GEMM: C[M,N] = A[M,K] * B[N,K]^T ----------------
// CTA tile 128x128, BK=64, 4-stage async pipeline (32 KB/stage), 8 compute warps + 1 producer.
#define TILE_BYTES  16384
#define STAGE_BYTES 32768      // A, B
#define NSTAGE      4
#define SMEM_REQ    (NSTAGE * STAGE_BYTES + 1024 + 128)

__global__ void __launch_bounds__(288, 1)
gemm_f16(const __half* __restrict__ A, const __half* __restrict__ B,
         float* __restrict__ C, int M, int N, int K) {
    extern __shared__ char smem_raw[];
    uint32_t sbase = (smem_u32(smem_raw) + 1023) & ~1023u;
    const int tid = threadIdx.x, wid = tid >> 5, lane = tid & 31;
    const int m0 = blockIdx.y * 128, n0 = blockIdx.x * 128;
    const int KT = K >> 6;
    const uint32_t bar = sbase + NSTAGE * STAGE_BYTES;
    // bar + 8*s: full[s]   bar + 64 + 8*s: empty[s]

    if (tid == 0) {
#pragma unroll
        for (int s = 0; s < NSTAGE; s++) {
            MBAR_INIT(bar + 8 * s, 1);
            MBAR_INIT(bar + 64 + 8 * s, 8);
        }
    }
    __syncthreads();

    if (wid == 8) {
        if (lane == 0) {
            const char* pA = (const char*)A + ((size_t)(m0 >> 7) * KT << 14);
            const char* pB = (const char*)B + ((size_t)(n0 >> 7) * KT << 14);
            int eph[NSTAGE] = {1, 1, 1, 1};
            int s = 0;
            for (int i = 0; i < KT; i++) {
                MBAR_WAIT(bar + 64 + 8 * s, eph[s]);
                eph[s] ^= 1;
                MBAR_EXPECT_TX(bar + 8 * s, (uint32_t)STAGE_BYTES);
                uint32_t st = sbase + s * STAGE_BYTES;
                size_t ko = (size_t)i << 14;
                BULK_G2S(st,              pA + ko, TILE_BYTES, bar + 8 * s);
                BULK_G2S(st + TILE_BYTES, pB + ko, TILE_BYTES, bar + 8 * s);
                if (++s == NSTAGE) s = 0;
            }
        }
        return;
    }

    // ---- compute warps 0..7: warp tile 64(m) x 32(n) ----
    const int wm = wid >> 2, wn = wid & 3;

    uint32_t a_off[4], a_msk[4];
#pragma unroll
    for (int i = 0; i < 4; i++) {
        uint32_t row = wm * 64 + i * 16 + (lane & 15);
        uint32_t off = (row << 7) | ((lane >> 4) << 4);
        a_off[i] = off;
        a_msk[i] = (off >> 3) & 0x70;
    }
    uint32_t b_off[2], b_msk[2];
#pragma unroll
    for (int p = 0; p < 2; p++) {
        uint32_t row = wn * 32 + p * 16 + ((lane >> 4) << 3) + (lane & 7);
        uint32_t off = (row << 7) | (((lane >> 3) & 1) << 4);
        b_off[p] = off;
        b_msk[p] = (off >> 3) & 0x70;
    }

    float acc[4][4][4];
#pragma unroll
    for (int i = 0; i < 4; i++)
#pragma unroll
        for (int j = 0; j < 4; j++)
#pragma unroll
            for (int e = 0; e < 4; e++) acc[i][j][e] = 0.f;

    int fph[NSTAGE] = {0, 0, 0, 0};
    int s = 0;
    for (int it = 0; it < KT; it++) {
        MBAR_WAIT(bar + 8 * s, fph[s]);
        fph[s] ^= 1;
        uint32_t sA = sbase + s * STAGE_BYTES;
        uint32_t sB = sA + TILE_BYTES;

#pragma unroll
        for (int ks = 0; ks < 4; ks++) {
            uint32_t kb = ks * 32;
            uint32_t ah[4][4], bh[4][2];
#pragma unroll
            for (int i = 0; i < 4; i++)
                ldsm_x4(ah[i], sA + ((a_off[i] + kb) ^ a_msk[i]));
#pragma unroll
            for (int p = 0; p < 2; p++) {
                uint32_t r[4];
                ldsm_x4(r, sB + ((b_off[p] + kb) ^ b_msk[p]));
                bh[2 * p][0] = r[0]; bh[2 * p][1] = r[1];
                bh[2 * p + 1][0] = r[2]; bh[2 * p + 1][1] = r[3];
            }
#pragma unroll
            for (int i = 0; i < 4; i++)
#pragma unroll
                for (int j = 0; j < 4; j++)
                    mma_f16(acc[i][j], ah[i], bh[j]);
        }
        __syncwarp();
        if (lane == 0) MBAR_ARRIVE(bar + 64 + 8 * s);
        if (++s == NSTAGE) s = 0;
    }

    // ---- epilogue: fragment -> C (row-major fp32) ----
    const int g_row = lane >> 2;
    const int g_col = (lane & 3) * 2;
#pragma unroll
    for (int i = 0; i < 4; i++) {
        size_t r0 = (size_t)m0 + wm * 64 + i * 16 + g_row;
#pragma unroll
        for (int j = 0; j < 4; j++) {
            int c = n0 + wn * 32 + j * 8 + g_col;
            float2 v0 = make_float2(acc[i][j][0], acc[i][j][1]);
            float2 v1 = make_float2(acc[i][j][2], acc[i][j][3]);
            *reinterpret_cast<float2*>(&C[r0 * N + c])       = v0;
            *reinterpret_cast<float2*>(&C[(r0 + 8) * N + c]) = v1;
        }
    }
}

// ---------------- launch ----------------
extern "C" void kernel_launch(void* const* d_in, const int* in_sizes, int n_in,
                              void* d_out, int out_size) {
    const float* x      = (const float*)d_in[0];
    const float* w_in   = (const float*)d_in[1];
    const float* w_out  = (const float*)d_in[2];
    const float* conv_w = (const float*)d_in[3];
    const float* conv_b = (const float*)d_in[4];
    const float* Dvec   = (const float*)d_in[5];
    float* out = (float*)d_out;

    float* xp; __half *xhi, *wihi, *hhi, *wohi;
    cudaGetSymbolAddress((void**)&xp,   g_xproj);
    cudaGetSymbolAddress((void**)&xhi,  g_x_hi);
    cudaGetSymbolAddress((void**)&wihi, g_wi_hi);
    cudaGetSymbolAddress((void**)&hhi,  g_h_hi);
    cudaGetSymbolAddress((void**)&wohi, g_wo_hi);

    cudaFuncSetAttribute(gemm_f16, cudaFuncAttributeMaxDynamicSharedMemorySize, SMEM_REQ);

    // converts (tiled+swizzled fp16)
    {
        int t8 = MTOT * K1 / 8;
        cvt_f16_tiled<<<(t8 + 255) / 256, 256>>>(x, xhi, t8, K1, 11);
    }
    {
        int t8 = N1 * K1 / 8;
        cvt_f16_tiled<<<(t8 + 255) / 256, 256>>>(w_in, wihi, t8, K1, 11);
    }
    {
        int t8 = N2 * K2 / 8;
        cvt_f16_tiled<<<(t8 + 255) / 256, 256>>>(w_out, wohi, t8, K2, 12);
    }

    // GEMM1: xproj[8192,8192] = x @ w_in^T
    gemm_f16<<<dim3(N1 / 128, MTOT / 128), 288, SMEM_REQ>>>(xhi, wihi, xp, MTOT, N1, K1);

    // conv + gate -> h (fp16)
    {
        int t8 = MTOT * DINNER / 8;
        conv_gate_f16<<<(t8 + 255) / 256, 256>>>(xp, conv_w, conv_b, Dvec, hhi);
    }

    // GEMM2: out[8192,2048] = h @ w_out^T
    gemm_f16<<<dim3(N2 / 128, MTOT / 128), 288, SMEM_REQ>>>(hhi, wohi, out, MTOT, N2, K2);
}